// round 2
// baseline (speedup 1.0000x reference)
#include <cuda_runtime.h>
#include <cstdint>

#define BB 8
#define SS 4096
#define DD 1024
#define MTOT (BB*SS)            // 32768 rows
#define NELEM (MTOT*DD)         // 33,554,432 elements
#define NK 1024                 // N == K == 1024

// ---------------- scratch (no allocations allowed) ----------------
__device__ float g_xg[NELEM];   // gelu(x), later reused as out_f
__device__ float g_u [NELEM];   // fwd branch pre-scan -> fwd states
__device__ float g_v [NELEM];   // bwd branch input
__device__ float g_gx[NELEM];   // gate_x -> scaled_in -> bwd states
__device__ float g_ga[NELEM];   // gate_a -> a (decay)
__device__ float g_of[NELEM];   // out_f

// ---------------- helpers ----------------
__device__ __forceinline__ float to_tf32(float x) {
    float r;
    asm("cvt.rna.tf32.f32 %0, %1;" : "=f"(r) : "f"(x));
    return r;
}

__device__ __forceinline__ void mma_tf32(float4& c, const uint32_t* a, const uint32_t* b) {
    asm volatile(
        "mma.sync.aligned.m16n8k8.row.col.f32.tf32.tf32.f32 "
        "{%0,%1,%2,%3},{%4,%5,%6,%7},{%8,%9},{%0,%1,%2,%3};\n"
        : "+f"(c.x), "+f"(c.y), "+f"(c.z), "+f"(c.w)
        : "r"(a[0]), "r"(a[1]), "r"(a[2]), "r"(a[3]), "r"(b[0]), "r"(b[1]));
}

// ---------------- elementwise: gelu (tanh approx, matches jax.nn.gelu) ----------------
__global__ void gelu_kernel(const float* __restrict__ x, float* __restrict__ y) {
    int i = blockIdx.x * blockDim.x + threadIdx.x;   // one float4 per thread
    float4 v = reinterpret_cast<const float4*>(x)[i];
    float* p = &v.x;
    float4 r;
    float* q = &r.x;
#pragma unroll
    for (int k = 0; k < 4; ++k) {
        float t = p[k];
        float inner = 0.7978845608028654f * (t + 0.044715f * t * t * t);
        q[k] = 0.5f * t * (1.0f + tanhf(inner));
    }
    reinterpret_cast<float4*>(y)[i] = r;
}

// ---------------- elementwise: RG-LRU gate math ----------------
// in:  v (g_v), gate_x (g_gx), gate_a (g_ga), a_param[d]
// out: a -> g_ga (in place), scaled_in -> g_gx (in place)
__global__ void gates_kernel(const float* __restrict__ v,
                             float* __restrict__ gx,
                             float* __restrict__ ga,
                             const float* __restrict__ a_param) {
    int i = blockIdx.x * blockDim.x + threadIdx.x;   // float4 index
    int d0 = (i * 4) & (DD - 1);
    float4 vv = reinterpret_cast<const float4*>(v)[i];
    float4 gxx = reinterpret_cast<float4*>(gx)[i];
    float4 gaa = reinterpret_cast<float4*>(ga)[i];
    float4 ap = *reinterpret_cast<const float4*>(&a_param[d0]);
    const float* pv = &vv.x; const float* pgx = &gxx.x;
    const float* pga = &gaa.x; const float* pap = &ap.x;
    float4 out_a, out_s;
    float* pa = &out_a.x; float* ps = &out_s.x;
#pragma unroll
    for (int k = 0; k < 4; ++k) {
        float sp = log1pf(expf(pap[k]));        // softplus(a_param)
        float la = -8.0f * pga[k] * sp;         // log_a
        float a = expf(la);
        pa[k] = a;
        ps[k] = sqrtf(1.0f - expf(2.0f * la)) * pgx[k] * pv[k];
    }
    reinterpret_cast<float4*>(ga)[i] = out_a;
    reinterpret_cast<float4*>(gx)[i] = out_s;
}

// ---------------- scans ----------------
// forward: h_t = a_fwd[d] * h_{t-1} + u_t, in place on u. grid(B), block(D)
__global__ void fwd_scan_kernel(float* __restrict__ u, const float* __restrict__ a_fwd) {
    int d = threadIdx.x;
    int b = blockIdx.x;
    float a = a_fwd[d];
    float h = 0.0f;
    size_t base = (size_t)b * SS * DD + d;
    for (int t = 0; t < SS; t += 4) {
        size_t i0 = base + (size_t)t * DD;
        float x0 = u[i0];
        float x1 = u[i0 + DD];
        float x2 = u[i0 + 2 * DD];
        float x3 = u[i0 + 3 * DD];
        h = fmaf(a, h, x0); u[i0]          = h;
        h = fmaf(a, h, x1); u[i0 + DD]     = h;
        h = fmaf(a, h, x2); u[i0 + 2 * DD] = h;
        h = fmaf(a, h, x3); u[i0 + 3 * DD] = h;
    }
}

// backward (reversed): h_t = a_t * h_{t+1} + s_t, in place on s. grid(B), block(D)
__global__ void bwd_scan_kernel(float* __restrict__ s, const float* __restrict__ a) {
    int d = threadIdx.x;
    int b = blockIdx.x;
    float h = 0.0f;
    size_t base = (size_t)b * SS * DD + d;
    for (int t = SS - 1; t >= 0; t -= 4) {
        size_t i0 = base + (size_t)t * DD;
        float a0 = a[i0];          float s0 = s[i0];
        float a1 = a[i0 - DD];     float s1 = s[i0 - DD];
        float a2 = a[i0 - 2 * DD]; float s2 = s[i0 - 2 * DD];
        float a3 = a[i0 - 3 * DD]; float s3 = s[i0 - 3 * DD];
        h = fmaf(a0, h, s0); s[i0]          = h;
        h = fmaf(a1, h, s1); s[i0 - DD]     = h;
        h = fmaf(a2, h, s2); s[i0 - 2 * DD] = h;
        h = fmaf(a3, h, s3); s[i0 - 3 * DD] = h;
    }
}

// ---------------- GEMM: C[M,N] = A[M,K] @ W[K,N] + bias, tf32 tensor cores ----
// CTA tile 128x128, K-tile 32, 8 warps (4 m x 2 n), warp tile 32x64.
// EPI: 0 = bias only, 1 = sigmoid(bias+acc), 2 = bias+acc+add1+add2
#define TM 128
#define TN 128
#define TK 32

template <int EPI>
__global__ __launch_bounds__(256)
void gemm_kernel(const float* __restrict__ A, const float* __restrict__ W,
                 const float* __restrict__ bias, float* __restrict__ C,
                 const float* __restrict__ add1, const float* __restrict__ add2) {
    __shared__ float As[TM][36];    // stride 36 -> conflict-free frag reads
    __shared__ float Bs[TK][136];   // stride 136 -> conflict-free frag reads

    const int tid  = threadIdx.x;
    const int wid  = tid >> 5;
    const int lane = tid & 31;
    const int wm   = wid & 3;       // warp row  (32 rows each)
    const int wn   = wid >> 2;      // warp col  (64 cols each)
    const int g    = lane >> 2;     // groupID
    const int tg   = lane & 3;      // threadID_in_group
    const int bm   = blockIdx.y;
    const int bn   = blockIdx.x;

    // global->reg staging for the software pipeline
    float4 ra[4], rb[4];

    // A tile addressing: 128 rows x 8 float4 of k
    int pa_r[4], pa_c[4], pb_k[4], pb_c[4];
#pragma unroll
    for (int it = 0; it < 4; ++it) {
        int p = tid + it * 256;
        pa_r[it] = p >> 3;  pa_c[it] = p & 7;    // A: row, k-float4
        pb_k[it] = p >> 5;  pb_c[it] = p & 31;   // B: k-row, n-float4
    }

    const float* Abase = A + (size_t)(bm * TM) * NK;
    const float* Wbase = W + bn * TN;

    auto load_tile = [&](int kt) {
#pragma unroll
        for (int it = 0; it < 4; ++it) {
            ra[it] = *reinterpret_cast<const float4*>(
                Abase + (size_t)pa_r[it] * NK + kt * TK + pa_c[it] * 4);
            rb[it] = *reinterpret_cast<const float4*>(
                Wbase + (size_t)(kt * TK + pb_k[it]) * NK + pb_c[it] * 4);
        }
    };
    auto store_tile = [&]() {
#pragma unroll
        for (int it = 0; it < 4; ++it) {
            float4 t;
            t.x = to_tf32(ra[it].x); t.y = to_tf32(ra[it].y);
            t.z = to_tf32(ra[it].z); t.w = to_tf32(ra[it].w);
            *reinterpret_cast<float4*>(&As[pa_r[it]][pa_c[it] * 4]) = t;
            float4 u;
            u.x = to_tf32(rb[it].x); u.y = to_tf32(rb[it].y);
            u.z = to_tf32(rb[it].z); u.w = to_tf32(rb[it].w);
            *reinterpret_cast<float4*>(&Bs[pb_k[it]][pb_c[it] * 4]) = u;
        }
    };

    float4 acc[2][8];
#pragma unroll
    for (int i = 0; i < 2; ++i)
#pragma unroll
        for (int j = 0; j < 8; ++j) acc[i][j] = make_float4(0.f, 0.f, 0.f, 0.f);

    load_tile(0);
    store_tile();
    __syncthreads();

    const int KT = NK / TK;   // 32
    for (int kt = 0; kt < KT; ++kt) {
        if (kt + 1 < KT) load_tile(kt + 1);   // prefetch next tile into regs

#pragma unroll
        for (int kk = 0; kk < TK; kk += 8) {
            uint32_t af[2][4], bf[8][2];
#pragma unroll
            for (int i = 0; i < 2; ++i) {
                int r0 = wm * 32 + i * 16 + g;
                af[i][0] = __float_as_uint(As[r0][kk + tg]);
                af[i][1] = __float_as_uint(As[r0 + 8][kk + tg]);
                af[i][2] = __float_as_uint(As[r0][kk + tg + 4]);
                af[i][3] = __float_as_uint(As[r0 + 8][kk + tg + 4]);
            }
#pragma unroll
            for (int j = 0; j < 8; ++j) {
                int n0 = wn * 64 + j * 8 + g;
                bf[j][0] = __float_as_uint(Bs[kk + tg][n0]);
                bf[j][1] = __float_as_uint(Bs[kk + tg + 4][n0]);
            }
#pragma unroll
            for (int i = 0; i < 2; ++i)
#pragma unroll
                for (int j = 0; j < 8; ++j) mma_tf32(acc[i][j], af[i], bf[j]);
        }

        __syncthreads();
        if (kt + 1 < KT) store_tile();
        __syncthreads();
    }

    // epilogue
#pragma unroll
    for (int i = 0; i < 2; ++i) {
        int row = bm * TM + wm * 32 + i * 16 + g;
#pragma unroll
        for (int j = 0; j < 8; ++j) {
            int col = bn * TN + wn * 64 + j * 8 + tg * 2;
            float b0 = bias[col], b1 = bias[col + 1];
            float v0 = acc[i][j].x + b0;
            float v1 = acc[i][j].y + b1;
            float v2 = acc[i][j].z + b0;
            float v3 = acc[i][j].w + b1;
            size_t i0 = (size_t)row * NK + col;
            size_t i1 = (size_t)(row + 8) * NK + col;
            if (EPI == 1) {
                v0 = 1.0f / (1.0f + expf(-v0));
                v1 = 1.0f / (1.0f + expf(-v1));
                v2 = 1.0f / (1.0f + expf(-v2));
                v3 = 1.0f / (1.0f + expf(-v3));
            } else if (EPI == 2) {
                float2 p0 = *reinterpret_cast<const float2*>(&add1[i0]);
                float2 p1 = *reinterpret_cast<const float2*>(&add1[i1]);
                float2 q0 = *reinterpret_cast<const float2*>(&add2[i0]);
                float2 q1 = *reinterpret_cast<const float2*>(&add2[i1]);
                v0 += p0.x + q0.x; v1 += p0.y + q0.y;
                v2 += p1.x + q1.x; v3 += p1.y + q1.y;
            }
            *reinterpret_cast<float2*>(&C[i0]) = make_float2(v0, v1);
            *reinterpret_cast<float2*>(&C[i1]) = make_float2(v2, v3);
        }
    }
}

// ---------------- launch ----------------
extern "C" void kernel_launch(void* const* d_in, const int* in_sizes, int n_in,
                              void* d_out, int out_size) {
    (void)in_sizes; (void)n_in; (void)out_size;
    const float* x       = (const float*)d_in[0];
    const float* a_fwd   = (const float*)d_in[1];
    const float* Wf1     = (const float*)d_in[2];
    const float* bf1     = (const float*)d_in[3];
    const float* Wf2     = (const float*)d_in[4];
    const float* bf2     = (const float*)d_in[5];
    const float* Wbx     = (const float*)d_in[6];
    const float* bbx     = (const float*)d_in[7];
    const float* Wgx     = (const float*)d_in[8];
    const float* bgx     = (const float*)d_in[9];
    const float* Wga     = (const float*)d_in[10];
    const float* bga     = (const float*)d_in[11];
    const float* a_param = (const float*)d_in[12];
    const float* Wb2     = (const float*)d_in[13];
    const float* bb2     = (const float*)d_in[14];
    float* out = (float*)d_out;

    float *xg, *u, *v, *gx, *ga, *of;
    cudaGetSymbolAddress((void**)&xg, g_xg);
    cudaGetSymbolAddress((void**)&u,  g_u);
    cudaGetSymbolAddress((void**)&v,  g_v);
    cudaGetSymbolAddress((void**)&gx, g_gx);
    cudaGetSymbolAddress((void**)&ga, g_ga);
    cudaGetSymbolAddress((void**)&of, g_of);

    const int n4 = NELEM / 4;               // 8,388,608 float4
    const int EW_BLOCKS = n4 / 256;         // 32768
    dim3 ggrid(NK / TN, MTOT / TM);         // (8, 256)

    gelu_kernel<<<EW_BLOCKS, 256>>>(x, xg);

    gemm_kernel<0><<<ggrid, 256>>>(xg, Wf1, bf1, u,  nullptr, nullptr);
    gemm_kernel<0><<<ggrid, 256>>>(xg, Wbx, bbx, v,  nullptr, nullptr);
    gemm_kernel<1><<<ggrid, 256>>>(v,  Wgx, bgx, gx, nullptr, nullptr);
    gemm_kernel<1><<<ggrid, 256>>>(v,  Wga, bga, ga, nullptr, nullptr);

    gates_kernel<<<EW_BLOCKS, 256>>>(v, gx, ga, a_param);

    fwd_scan_kernel<<<BB, DD>>>(u, a_fwd);
    bwd_scan_kernel<<<BB, DD>>>(gx, ga);

    gemm_kernel<0><<<ggrid, 256>>>(u,  Wf2, bf2, of, nullptr, nullptr);
    gemm_kernel<2><<<ggrid, 256>>>(gx, Wb2, bb2, out, of, x);
}

// round 4
// speedup vs baseline: 1.3666x; 1.3666x over previous
#include <cuda_runtime.h>
#include <cstdint>

#define BB 8
#define SS 4096
#define DD 1024
#define MTOT (BB*SS)            // 32768
#define NELEM (MTOT*DD)
#define NK 1024

#define NCH 32
#define CHL 128                 // SS/NCH

// ---- GEMM tiling ----
#define TM 128
#define TN 128
#define TKC 32
#define KT (NK/TKC)             // 32
#define STAGES 3
#define AST 36                  // A smem row stride (floats), 144B (16B aligned)
#define BST 136                 // B smem row stride (floats), 544B (16B aligned)
#define ABYT (TM*AST*4)         // 18432
#define BBYT (TKC*BST*4)        // 17408
#define STBYT (ABYT+BBYT)       // 35840
#define SMEM_REQ (STAGES*STBYT) // 107520

// ---------------- scratch ----------------
__device__ float g_xg[NELEM];
__device__ float g_u [NELEM];
__device__ float g_v [NELEM];
__device__ float g_gx[NELEM];
__device__ float g_ga[NELEM];
__device__ float g_of[NELEM];
__device__ float g_wt[6*NK*NK];          // tf32-rounded weights
__device__ float g_end[BB*NCH*DD];
__device__ float g_P  [BB*NCH*DD];
__device__ float g_cr [BB*NCH*DD];

// ---------------- helpers ----------------
__device__ __forceinline__ float to_tf32(float x) {
    float r; asm("cvt.rna.tf32.f32 %0, %1;" : "=f"(r) : "f"(x)); return r;
}
__device__ __forceinline__ uint32_t smem_u32(const void* p) {
    uint32_t a;
    asm("{ .reg .u64 t; cvta.to.shared.u64 t, %1; cvt.u32.u64 %0, t; }" : "=r"(a) : "l"(p));
    return a;
}
__device__ __forceinline__ void cp16(uint32_t saddr, const void* gaddr) {
    asm volatile("cp.async.cg.shared.global [%0], [%1], 16;" :: "r"(saddr), "l"(gaddr));
}
__device__ __forceinline__ void cp_commit() {
    asm volatile("cp.async.commit_group;" ::: "memory");
}
__device__ __forceinline__ void cp_wait1() {
    asm volatile("cp.async.wait_group 1;" ::: "memory");
}
__device__ __forceinline__ void mma_tf32(float4& c, const uint32_t* a, const uint32_t* b) {
    asm volatile(
        "mma.sync.aligned.m16n8k8.row.col.f32.tf32.tf32.f32 "
        "{%0,%1,%2,%3},{%4,%5,%6,%7},{%8,%9},{%0,%1,%2,%3};\n"
        : "+f"(c.x), "+f"(c.y), "+f"(c.z), "+f"(c.w)
        : "r"(a[0]), "r"(a[1]), "r"(a[2]), "r"(a[3]), "r"(b[0]), "r"(b[1]));
}

// ---------------- weight prep: round to tf32 ----------------
__global__ void roundw_kernel(const float* __restrict__ src, float* __restrict__ dst) {
    int i = blockIdx.x * blockDim.x + threadIdx.x;
    float4 v = reinterpret_cast<const float4*>(src)[i];
    v.x = to_tf32(v.x); v.y = to_tf32(v.y); v.z = to_tf32(v.z); v.w = to_tf32(v.w);
    reinterpret_cast<float4*>(dst)[i] = v;
}

// ---------------- gelu (tanh approx), output rounded to tf32 ----------------
__global__ void gelu_kernel(const float* __restrict__ x, float* __restrict__ y) {
    int i = blockIdx.x * blockDim.x + threadIdx.x;
    float4 v = reinterpret_cast<const float4*>(x)[i];
    float* p = &v.x;
    float4 r; float* q = &r.x;
#pragma unroll
    for (int k = 0; k < 4; ++k) {
        float t = p[k];
        float inner = 0.7978845608028654f * (t + 0.044715f * t * t * t);
        q[k] = to_tf32(0.5f * t * (1.0f + tanhf(inner)));
    }
    reinterpret_cast<float4*>(y)[i] = r;
}

// ---------------- RG-LRU gate math ----------------
__global__ void gates_kernel(const float* __restrict__ v,
                             float* __restrict__ gx,
                             float* __restrict__ ga,
                             const float* __restrict__ a_param) {
    int i = blockIdx.x * blockDim.x + threadIdx.x;
    int d0 = (i * 4) & (DD - 1);
    float4 vv  = reinterpret_cast<const float4*>(v)[i];
    float4 gxx = reinterpret_cast<float4*>(gx)[i];
    float4 gaa = reinterpret_cast<float4*>(ga)[i];
    float4 ap  = *reinterpret_cast<const float4*>(&a_param[d0]);
    const float* pv = &vv.x; const float* pgx = &gxx.x;
    const float* pga = &gaa.x; const float* pap = &ap.x;
    float4 oa, os; float* pa = &oa.x; float* ps = &os.x;
#pragma unroll
    for (int k = 0; k < 4; ++k) {
        float sp = log1pf(expf(pap[k]));
        float la = -8.0f * pga[k] * sp;
        pa[k] = expf(la);
        ps[k] = sqrtf(1.0f - expf(2.0f * la)) * pgx[k] * pv[k];
    }
    reinterpret_cast<float4*>(ga)[i] = oa;
    reinterpret_cast<float4*>(gx)[i] = os;
}

// ---------------- chunked scans (3-pass) ----------------
__global__ void fwd_p1(const float* __restrict__ u, const float* __restrict__ a_fwd,
                       float* __restrict__ endv, float* __restrict__ Pv) {
    int d = threadIdx.x, bc = blockIdx.x;
    float a = a_fwd[d];
    size_t base = (size_t)bc * CHL * DD + d;
    float h = 0.f;
#pragma unroll 4
    for (int t = 0; t < CHL; ++t) h = fmaf(a, h, u[base + (size_t)t * DD]);
    float p = a;
#pragma unroll
    for (int i = 0; i < 7; ++i) p *= p;   // a^128
    endv[bc * DD + d] = h; Pv[bc * DD + d] = p;
}

__global__ void fwd_p2(const float* __restrict__ endv, const float* __restrict__ Pv,
                       float* __restrict__ cr) {
    int g = blockIdx.x * blockDim.x + threadIdx.x;
    int b = g >> 10, d = g & 1023;
    float acc = 0.f;
    for (int c = 0; c < NCH; ++c) {
        size_t i = (size_t)(b * NCH + c) * DD + d;
        cr[i] = acc;
        acc = endv[i] + Pv[i] * acc;
    }
}

// re-scan with carry; output rounded to tf32 (feeds GEMM)
__global__ void fwd_p3(float* __restrict__ u, const float* __restrict__ a_fwd,
                       const float* __restrict__ cr) {
    int d = threadIdx.x, bc = blockIdx.x;
    float a = a_fwd[d];
    size_t base = (size_t)bc * CHL * DD + d;
    float h = cr[bc * DD + d];
#pragma unroll 4
    for (int t = 0; t < CHL; ++t) {
        size_t i = base + (size_t)t * DD;
        h = fmaf(a, h, u[i]);
        u[i] = to_tf32(h);
    }
}

__global__ void bwd_p1(const float* __restrict__ s, const float* __restrict__ a,
                       float* __restrict__ endv, float* __restrict__ Pv) {
    int d = threadIdx.x, bc = blockIdx.x;
    size_t base = (size_t)bc * CHL * DD + d;
    float h = 0.f, p = 1.f;
#pragma unroll 4
    for (int t = CHL - 1; t >= 0; --t) {
        size_t i = base + (size_t)t * DD;
        float av = a[i];
        h = fmaf(av, h, s[i]);
        p *= av;
    }
    endv[bc * DD + d] = h; Pv[bc * DD + d] = p;
}

__global__ void bwd_p2(const float* __restrict__ endv, const float* __restrict__ Pv,
                       float* __restrict__ cr) {
    int g = blockIdx.x * blockDim.x + threadIdx.x;
    int b = g >> 10, d = g & 1023;
    float acc = 0.f;
    for (int c = NCH - 1; c >= 0; --c) {
        size_t i = (size_t)(b * NCH + c) * DD + d;
        cr[i] = acc;
        acc = endv[i] + Pv[i] * acc;
    }
}

__global__ void bwd_p3(float* __restrict__ s, const float* __restrict__ a,
                       const float* __restrict__ cr) {
    int d = threadIdx.x, bc = blockIdx.x;
    size_t base = (size_t)bc * CHL * DD + d;
    float h = cr[bc * DD + d];
#pragma unroll 4
    for (int t = CHL - 1; t >= 0; --t) {
        size_t i = base + (size_t)t * DD;
        h = fmaf(a[i], h, s[i]);
        s[i] = to_tf32(h);
    }
}

// ---------------- GEMM: C[M,N] = A[M,K] @ W[K,N] + bias ----------------
// Operands MUST already be tf32-rounded (raw cp.async copies).
// EPI: 0 = bias, 1 = sigmoid(acc+bias), 2 = acc+bias+add1+add2
// ROUND: round stored output to tf32
template <int EPI, int ROUND>
__global__ __launch_bounds__(256, 2)
void gemm_kernel(const float* __restrict__ A, const float* __restrict__ W,
                 const float* __restrict__ bias, float* __restrict__ C,
                 const float* __restrict__ add1, const float* __restrict__ add2) {
    extern __shared__ char sm[];
    const uint32_t smb = smem_u32(sm);

    const int tid  = threadIdx.x;
    const int wid  = tid >> 5;
    const int lane = tid & 31;
    const int wm   = wid & 3;
    const int wn   = wid >> 2;
    const int g    = lane >> 2;
    const int tg   = lane & 3;
    const int bm   = blockIdx.y;
    const int bn   = blockIdx.x;

    // per-thread copy slots
    const int ar = tid >> 3, ac4 = tid & 7;    // A: rows ar+32*it, float4 col ac4
    const int bk = tid >> 5, bn4 = tid & 31;   // B: k rows bk+8*it? (1024/256=4 -> k = (p)>>5)

    const float* Abase = A + (size_t)(bm * TM) * NK;
    const float* Wbase = W + bn * TN;

    // smem offsets (bytes) for this thread's 4 A slots + 4 B slots
    uint32_t sA[4], sB[4];
    const float* gA[4]; const float* gB[4];
#pragma unroll
    for (int it = 0; it < 4; ++it) {
        int p = tid + it * 256;
        int arow = p >> 3, acol = p & 7;          // A[128][8 float4]
        int brow = p >> 5, bcol = p & 31;         // B[32][32 float4]
        sA[it] = (uint32_t)(arow * AST + acol * 4) * 4u;
        sB[it] = (uint32_t)(ABYT + (brow * BST + bcol * 4) * 4);
        gA[it] = Abase + (size_t)arow * NK + acol * 4;
        gB[it] = Wbase + (size_t)brow * NK + bcol * 4;
    }

    auto issue = [&](int kt) {
        const int buf = kt % STAGES;
        const uint32_t sb = smb + buf * STBYT;
        const float* ga0 = gA[0] + kt * TKC;     // A advances 32 floats in k
        const float* ga1 = gA[1] + kt * TKC;
        const float* ga2 = gA[2] + kt * TKC;
        const float* ga3 = gA[3] + kt * TKC;
        const size_t bo = (size_t)kt * TKC * NK; // B advances 32 rows
        cp16(sb + sA[0], ga0);
        cp16(sb + sA[1], ga1);
        cp16(sb + sA[2], ga2);
        cp16(sb + sA[3], ga3);
        cp16(sb + sB[0], gB[0] + bo);
        cp16(sb + sB[1], gB[1] + bo);
        cp16(sb + sB[2], gB[2] + bo);
        cp16(sb + sB[3], gB[3] + bo);
    };

    float4 acc[2][8];
#pragma unroll
    for (int i = 0; i < 2; ++i)
#pragma unroll
        for (int j = 0; j < 8; ++j) acc[i][j] = make_float4(0.f, 0.f, 0.f, 0.f);

    issue(0); cp_commit();
    issue(1); cp_commit();

    // fragment base pointers
    const int arow0 = wm * 32 + g;
    const int ncol0 = wn * 64 + g;

    for (int kt = 0; kt < KT; ++kt) {
        cp_wait1();
        __syncthreads();
        if (kt + 2 < KT) issue(kt + 2);
        cp_commit();

        const float* As0 = (const float*)(sm + (kt % STAGES) * STBYT);
        const float* Bs0 = As0 + TM * AST;
        const float* aR = As0 + arow0 * AST + tg;
        const float* bR = Bs0 + tg * BST + ncol0;

#pragma unroll
        for (int kk = 0; kk < TKC; kk += 8) {
            uint32_t af[2][4], bf[8][2];
#pragma unroll
            for (int i = 0; i < 2; ++i) {
                const float* a0 = aR + i * 16 * AST + kk;
                af[i][0] = __float_as_uint(a0[0]);
                af[i][1] = __float_as_uint(a0[8 * AST]);
                af[i][2] = __float_as_uint(a0[4]);
                af[i][3] = __float_as_uint(a0[8 * AST + 4]);
            }
#pragma unroll
            for (int j = 0; j < 8; ++j) {
                const float* b0 = bR + kk * BST + j * 8;
                bf[j][0] = __float_as_uint(b0[0]);
                bf[j][1] = __float_as_uint(b0[4 * BST]);
            }
#pragma unroll
            for (int i = 0; i < 2; ++i)
#pragma unroll
                for (int j = 0; j < 8; ++j) mma_tf32(acc[i][j], af[i], bf[j]);
        }
        __syncthreads();
    }

    // epilogue
#pragma unroll
    for (int i = 0; i < 2; ++i) {
        int row = bm * TM + wm * 32 + i * 16 + g;
#pragma unroll
        for (int j = 0; j < 8; ++j) {
            int col = bn * TN + wn * 64 + j * 8 + tg * 2;
            float b0 = bias[col], b1 = bias[col + 1];
            float v0 = acc[i][j].x + b0;
            float v1 = acc[i][j].y + b1;
            float v2 = acc[i][j].z + b0;
            float v3 = acc[i][j].w + b1;
            size_t i0 = (size_t)row * NK + col;
            size_t i1 = (size_t)(row + 8) * NK + col;
            if (EPI == 1) {
                v0 = 1.0f / (1.0f + expf(-v0));
                v1 = 1.0f / (1.0f + expf(-v1));
                v2 = 1.0f / (1.0f + expf(-v2));
                v3 = 1.0f / (1.0f + expf(-v3));
            } else if (EPI == 2) {
                float2 p0 = *reinterpret_cast<const float2*>(&add1[i0]);
                float2 p1 = *reinterpret_cast<const float2*>(&add1[i1]);
                float2 q0 = *reinterpret_cast<const float2*>(&add2[i0]);
                float2 q1 = *reinterpret_cast<const float2*>(&add2[i1]);
                v0 += p0.x + q0.x; v1 += p0.y + q0.y;
                v2 += p1.x + q1.x; v3 += p1.y + q1.y;
            }
            if (ROUND) {
                v0 = to_tf32(v0); v1 = to_tf32(v1);
                v2 = to_tf32(v2); v3 = to_tf32(v3);
            }
            *reinterpret_cast<float2*>(&C[i0]) = make_float2(v0, v1);
            *reinterpret_cast<float2*>(&C[i1]) = make_float2(v2, v3);
        }
    }
}

// ---------------- launch ----------------
extern "C" void kernel_launch(void* const* d_in, const int* in_sizes, int n_in,
                              void* d_out, int out_size) {
    (void)in_sizes; (void)n_in; (void)out_size;
    const float* x       = (const float*)d_in[0];
    const float* a_fwd   = (const float*)d_in[1];
    const float* Wf1     = (const float*)d_in[2];
    const float* bf1     = (const float*)d_in[3];
    const float* Wf2     = (const float*)d_in[4];
    const float* bf2     = (const float*)d_in[5];
    const float* Wbx     = (const float*)d_in[6];
    const float* bbx     = (const float*)d_in[7];
    const float* Wgx     = (const float*)d_in[8];
    const float* bgx     = (const float*)d_in[9];
    const float* Wga     = (const float*)d_in[10];
    const float* bga     = (const float*)d_in[11];
    const float* a_param = (const float*)d_in[12];
    const float* Wb2     = (const float*)d_in[13];
    const float* bb2     = (const float*)d_in[14];
    float* out = (float*)d_out;

    float *xg, *u, *v, *gx, *ga, *of, *wt, *endv, *Pv, *cr;
    cudaGetSymbolAddress((void**)&xg, g_xg);
    cudaGetSymbolAddress((void**)&u,  g_u);
    cudaGetSymbolAddress((void**)&v,  g_v);
    cudaGetSymbolAddress((void**)&gx, g_gx);
    cudaGetSymbolAddress((void**)&ga, g_ga);
    cudaGetSymbolAddress((void**)&of, g_of);
    cudaGetSymbolAddress((void**)&wt, g_wt);
    cudaGetSymbolAddress((void**)&endv, g_end);
    cudaGetSymbolAddress((void**)&Pv,  g_P);
    cudaGetSymbolAddress((void**)&cr,  g_cr);

    cudaFuncSetAttribute(gemm_kernel<0,0>, cudaFuncAttributeMaxDynamicSharedMemorySize, SMEM_REQ);
    cudaFuncSetAttribute(gemm_kernel<0,1>, cudaFuncAttributeMaxDynamicSharedMemorySize, SMEM_REQ);
    cudaFuncSetAttribute(gemm_kernel<1,0>, cudaFuncAttributeMaxDynamicSharedMemorySize, SMEM_REQ);
    cudaFuncSetAttribute(gemm_kernel<2,0>, cudaFuncAttributeMaxDynamicSharedMemorySize, SMEM_REQ);

    const int WB = (NK * NK / 4) / 256;     // weight-round blocks
    roundw_kernel<<<WB, 256>>>(Wf1, wt + 0ull * NK * NK);
    roundw_kernel<<<WB, 256>>>(Wbx, wt + 1ull * NK * NK);
    roundw_kernel<<<WB, 256>>>(Wgx, wt + 2ull * NK * NK);
    roundw_kernel<<<WB, 256>>>(Wga, wt + 3ull * NK * NK);
    roundw_kernel<<<WB, 256>>>(Wf2, wt + 4ull * NK * NK);
    roundw_kernel<<<WB, 256>>>(Wb2, wt + 5ull * NK * NK);

    const int EW_BLOCKS = (NELEM / 4) / 256;
    gelu_kernel<<<EW_BLOCKS, 256>>>(x, xg);

    dim3 ggrid(NK / TN, MTOT / TM);   // (8, 256)
    gemm_kernel<0,0><<<ggrid, 256, SMEM_REQ>>>(xg, wt + 0ull*NK*NK, bf1, u,  nullptr, nullptr);
    gemm_kernel<0,1><<<ggrid, 256, SMEM_REQ>>>(xg, wt + 1ull*NK*NK, bbx, v,  nullptr, nullptr);
    gemm_kernel<1,0><<<ggrid, 256, SMEM_REQ>>>(v,  wt + 2ull*NK*NK, bgx, gx, nullptr, nullptr);
    gemm_kernel<1,0><<<ggrid, 256, SMEM_REQ>>>(v,  wt + 3ull*NK*NK, bga, ga, nullptr, nullptr);

    gates_kernel<<<EW_BLOCKS, 256>>>(v, gx, ga, a_param);

    fwd_p1<<<BB * NCH, DD>>>(u, a_fwd, endv, Pv);
    fwd_p2<<<BB, DD>>>(endv, Pv, cr);
    fwd_p3<<<BB * NCH, DD>>>(u, a_fwd, cr);

    bwd_p1<<<BB * NCH, DD>>>(gx, ga, endv, Pv);
    bwd_p2<<<BB, DD>>>(endv, Pv, cr);
    bwd_p3<<<BB * NCH, DD>>>(gx, ga, cr);

    gemm_kernel<0,0><<<ggrid, 256, SMEM_REQ>>>(u,  wt + 4ull*NK*NK, bf2, of, nullptr, nullptr);
    gemm_kernel<2,0><<<ggrid, 256, SMEM_REQ>>>(gx, wt + 5ull*NK*NK, bb2, out, of, x);
}